// round 3
// baseline (speedup 1.0000x reference)
#include <cuda_runtime.h>

#define BB 8
#define TT 2048
#define CC 1024
#define HH 128
#define BT (BB*TT)
#define SCALE 0.08838834764831845f

#define QTILE 64
#define KTILE 64
#define LDT 132   // padded row stride (floats) for 128-wide tiles, 16B aligned
#define LDSS 68   // padded row stride for 64-wide score tile

// Scratch for projections (static device memory: allowed; no allocation)
__device__ float g_q[BT * HH];
__device__ float g_k[BT * HH];
__device__ float g_v[BT * HH];

// ---------------------------------------------------------------------------
// Projection GEMM: out[mat] = x @ W[mat],  M=16384, K=1024, N=128
// tile: 128 rows x 128 cols, 256 threads, 8x8 per-thread microtile
// ---------------------------------------------------------------------------
__global__ __launch_bounds__(256) void proj_kernel(
    const float* __restrict__ x,
    const float* __restrict__ Wk,
    const float* __restrict__ Wq,
    const float* __restrict__ Wv)
{
    __shared__ float sX[128 * 17];   // 128 rows x 16 k, pad 17
    __shared__ float sW[16 * 128];   // 16 k x 128 cols

    const int mat = blockIdx.y;      // 0=q, 1=k, 2=v
    const float* W  = (mat == 0) ? Wq : (mat == 1) ? Wk : Wv;
    float* out      = (mat == 0) ? g_q : (mat == 1) ? g_k : g_v;

    const int row0 = blockIdx.x * 128;
    const int tid = threadIdx.x;
    const int ty = tid >> 4;         // 0..15 -> rows ty*8..ty*8+7
    const int tx = tid & 15;         // 0..15 -> cols tx + j*16

    float acc[8][8];
#pragma unroll
    for (int i = 0; i < 8; i++)
#pragma unroll
        for (int j = 0; j < 8; j++) acc[i][j] = 0.f;

    for (int k0 = 0; k0 < CC; k0 += 16) {
        // load X tile 128x16 (512 float4, 2 per thread)
#pragma unroll
        for (int it = 0; it < 2; it++) {
            int idx = tid + it * 256;
            int r = idx >> 2;
            int c4 = (idx & 3) * 4;
            float4 xv = *(const float4*)(x + (size_t)(row0 + r) * CC + k0 + c4);
            sX[r * 17 + c4 + 0] = xv.x;
            sX[r * 17 + c4 + 1] = xv.y;
            sX[r * 17 + c4 + 2] = xv.z;
            sX[r * 17 + c4 + 3] = xv.w;
        }
        // load W tile 16x128 (512 float4, 2 per thread)
#pragma unroll
        for (int it = 0; it < 2; it++) {
            int idx = tid + it * 256;
            int r = idx >> 5;
            int c4 = (idx & 31) * 4;
            *(float4*)&sW[r * 128 + c4] =
                *(const float4*)(W + (size_t)(k0 + r) * HH + c4);
        }
        __syncthreads();

#pragma unroll
        for (int k = 0; k < 16; k++) {
            float a[8], b[8];
#pragma unroll
            for (int i = 0; i < 8; i++) a[i] = sX[(ty * 8 + i) * 17 + k];
#pragma unroll
            for (int j = 0; j < 8; j++) b[j] = sW[k * 128 + tx + j * 16];
#pragma unroll
            for (int i = 0; i < 8; i++)
#pragma unroll
                for (int j = 0; j < 8; j++) acc[i][j] += a[i] * b[j];
        }
        __syncthreads();
    }

#pragma unroll
    for (int i = 0; i < 8; i++)
#pragma unroll
        for (int j = 0; j < 8; j++)
            out[(size_t)(row0 + ty * 8 + i) * HH + tx + j * 16] = acc[i][j];
}

// ---------------------------------------------------------------------------
// Flash attention (causal), fp32. One block = (batch b, 64 query rows).
// 256 threads: 16x16 grid; S phase: 4x4 per thread; PV phase: 4 rows x 8 cols.
// Softmax: 4 lanes per row, shuffle-reduced (all 256 threads active).
// ---------------------------------------------------------------------------
__global__ __launch_bounds__(256) void flash_kernel(float* __restrict__ out)
{
    extern __shared__ float sm[];
    float* sQ   = sm;                         // QTILE * LDT
    float* sK   = sQ + QTILE * LDT;           // QTILE * LDT
    float* sV   = sK + QTILE * LDT;           // QTILE * LDT
    float* sS   = sV + QTILE * LDT;           // QTILE * LDSS
    float* mrow = sS + QTILE * LDSS;          // QTILE
    float* lrow = mrow + QTILE;               // QTILE
    float* frow = lrow + QTILE;               // QTILE

    const int iq = blockIdx.x;
    const int b  = blockIdx.y;
    const int tid = threadIdx.x;
    const int ty = tid >> 4;
    const int tx = tid & 15;

    const float* Qg = g_q + ((size_t)b * TT + iq * QTILE) * HH;

    // load Q tile 64x128 (2048 float4, 8 per thread)
#pragma unroll
    for (int it = 0; it < 8; it++) {
        int idx = tid + it * 256;
        int r = idx >> 5;
        int c4 = (idx & 31) * 4;
        *(float4*)&sQ[r * LDT + c4] = *(const float4*)(Qg + (size_t)r * HH + c4);
    }
    if (tid < QTILE) { mrow[tid] = -1e30f; lrow[tid] = 0.f; }

    float o[4][8];
#pragma unroll
    for (int i = 0; i < 4; i++)
#pragma unroll
        for (int j = 0; j < 8; j++) o[i][j] = 0.f;

    for (int jt = 0; jt <= iq; jt++) {
        __syncthreads();   // previous iteration done with sK/sV/sS
        const float* Kg = g_k + ((size_t)b * TT + jt * KTILE) * HH;
        const float* Vg = g_v + ((size_t)b * TT + jt * KTILE) * HH;
#pragma unroll
        for (int it = 0; it < 8; it++) {
            int idx = tid + it * 256;
            int r = idx >> 5;
            int c4 = (idx & 31) * 4;
            *(float4*)&sK[r * LDT + c4] = *(const float4*)(Kg + (size_t)r * HH + c4);
            *(float4*)&sV[r * LDT + c4] = *(const float4*)(Vg + (size_t)r * HH + c4);
        }
        __syncthreads();

        // S = Q K^T  (64x64, k=128), float4 over k
        float s[4][4];
#pragma unroll
        for (int i = 0; i < 4; i++)
#pragma unroll
            for (int j = 0; j < 4; j++) s[i][j] = 0.f;

        for (int k4 = 0; k4 < HH; k4 += 4) {
            float4 a[4], kk[4];
#pragma unroll
            for (int i = 0; i < 4; i++)
                a[i] = *(float4*)&sQ[(ty * 4 + i) * LDT + k4];
#pragma unroll
            for (int j = 0; j < 4; j++)
                kk[j] = *(float4*)&sK[(tx + j * 16) * LDT + k4];
#pragma unroll
            for (int i = 0; i < 4; i++)
#pragma unroll
                for (int j = 0; j < 4; j++) {
                    s[i][j] += a[i].x * kk[j].x;
                    s[i][j] += a[i].y * kk[j].y;
                    s[i][j] += a[i].z * kk[j].z;
                    s[i][j] += a[i].w * kk[j].w;
                }
        }
        // scale + causal mask, write to sS
#pragma unroll
        for (int i = 0; i < 4; i++) {
            int grow = iq * QTILE + ty * 4 + i;
#pragma unroll
            for (int j = 0; j < 4; j++) {
                int gcol = jt * KTILE + tx + j * 16;
                float v = (gcol <= grow) ? s[i][j] * SCALE : -1e30f;
                sS[(ty * 4 + i) * LDSS + tx + j * 16] = v;
            }
        }
        __syncthreads();

        // online softmax: 4 lanes per row, all 256 threads active.
        // addresses r*68 + sub + 4j -> banks (4r + sub + 4j) % 32: conflict-free.
        {
            int r = tid >> 2;
            int sub = tid & 3;
            float mold = mrow[r];
            float mt = mold;
#pragma unroll
            for (int j = 0; j < 16; j++)
                mt = fmaxf(mt, sS[r * LDSS + sub + 4 * j]);
            mt = fmaxf(mt, __shfl_xor_sync(0xFFFFFFFFu, mt, 1));
            mt = fmaxf(mt, __shfl_xor_sync(0xFFFFFFFFu, mt, 2));
            float ssum = 0.f;
#pragma unroll
            for (int j = 0; j < 16; j++) {
                float p = __expf(sS[r * LDSS + sub + 4 * j] - mt);
                sS[r * LDSS + sub + 4 * j] = p;
                ssum += p;
            }
            ssum += __shfl_xor_sync(0xFFFFFFFFu, ssum, 1);
            ssum += __shfl_xor_sync(0xFFFFFFFFu, ssum, 2);
            if (sub == 0) {
                float f = __expf(mold - mt);
                mrow[r] = mt;
                lrow[r] = lrow[r] * f + ssum;
                frow[r] = f;
            }
        }
        __syncthreads();

        // rescale O, then O += P @ V  (64x128, k=64)
        float fr[4];
#pragma unroll
        for (int i = 0; i < 4; i++) fr[i] = frow[ty * 4 + i];
#pragma unroll
        for (int i = 0; i < 4; i++)
#pragma unroll
            for (int j = 0; j < 8; j++) o[i][j] *= fr[i];

        for (int k = 0; k < KTILE; k++) {
            float a[4], vv[8];
#pragma unroll
            for (int i = 0; i < 4; i++) a[i] = sS[(ty * 4 + i) * LDSS + k];
#pragma unroll
            for (int j = 0; j < 8; j++) vv[j] = sV[k * LDT + tx + j * 16];
#pragma unroll
            for (int i = 0; i < 4; i++)
#pragma unroll
                for (int j = 0; j < 8; j++) o[i][j] += a[i] * vv[j];
        }
    }

    __syncthreads();
    float inv[4];
#pragma unroll
    for (int i = 0; i < 4; i++) inv[i] = 1.f / lrow[ty * 4 + i];

    float* Og = out + ((size_t)b * TT + iq * QTILE) * HH;
#pragma unroll
    for (int i = 0; i < 4; i++)
#pragma unroll
        for (int j = 0; j < 8; j++)
            Og[(size_t)(ty * 4 + i) * HH + tx + j * 16] = o[i][j] * inv[i];
}

// ---------------------------------------------------------------------------
extern "C" void kernel_launch(void* const* d_in, const int* in_sizes, int n_in,
                              void* d_out, int out_size)
{
    const float* x  = (const float*)d_in[0];
    const float* Wk = (const float*)d_in[1];
    const float* Wq = (const float*)d_in[2];
    const float* Wv = (const float*)d_in[3];
    float* out = (float*)d_out;

    const int smem_bytes = (QTILE * LDT * 3 + QTILE * LDSS + 3 * QTILE) * 4; // 119552
    (void)cudaFuncSetAttribute(flash_kernel,
                               cudaFuncAttributeMaxDynamicSharedMemorySize,
                               smem_bytes);

    dim3 g1(BT / 128, 3);
    proj_kernel<<<g1, 256>>>(x, Wk, Wq, Wv);

    dim3 g2(TT / QTILE, BB);
    flash_kernel<<<g2, 256, smem_bytes>>>(out);
}

// round 4
// speedup vs baseline: 2.4451x; 2.4451x over previous
#include <cuda_runtime.h>
#include <cstdint>

#define BB 8
#define TT 2048
#define CC 1024
#define HH 128
#define BT (BB*TT)
#define SCALE 0.08838834764831845f

#define PX_LD 36     // sX row stride (32 k + 4 pad): bank = 4m+k, conflict-free
#define PW_LD 136    // sW row stride (128 n + 8 pad): bank = 8k+n, conflict-free
#define LDT 132      // flash Q/K/V row stride (128 + 4): bank = 4r+c, conflict-free
#define LDSS 68      // score tile row stride (64 + 4)

// q/k/v scratch stored as tf32 bit patterns (static device mem: allowed)
__device__ uint32_t g_q[BT * HH];
__device__ uint32_t g_k[BT * HH];
__device__ uint32_t g_v[BT * HH];

__device__ __forceinline__ uint32_t f2tf(float x) {
    uint32_t r;
    asm("cvt.rna.tf32.f32 %0, %1;" : "=r"(r) : "f"(x));
    return r;
}

// D += A*B, m16n8k8, A row-major 16x8 tf32, B col-major 8x8 tf32, fp32 accum
__device__ __forceinline__ void mma8(float* c, uint32_t a0, uint32_t a1,
                                     uint32_t a2, uint32_t a3,
                                     uint32_t b0, uint32_t b1) {
    asm volatile(
        "mma.sync.aligned.m16n8k8.row.col.f32.tf32.tf32.f32 "
        "{%0,%1,%2,%3},{%4,%5,%6,%7},{%8,%9},{%0,%1,%2,%3};"
        : "+f"(c[0]), "+f"(c[1]), "+f"(c[2]), "+f"(c[3])
        : "r"(a0), "r"(a1), "r"(a2), "r"(a3), "r"(b0), "r"(b1));
}

// ---------------------------------------------------------------------------
// Projection: out[mat] = tf32(x @ W[mat]).  M=16384, K=1024, N=128.
// Block tile 128x128, 256 thr (8 warps), warp tile 32x64, K-step 32.
// ---------------------------------------------------------------------------
__global__ __launch_bounds__(256) void proj_kernel(
    const float* __restrict__ x,
    const float* __restrict__ Wk,
    const float* __restrict__ Wq,
    const float* __restrict__ Wv)
{
    __shared__ uint32_t sX[128 * PX_LD];
    __shared__ uint32_t sW[32 * PW_LD];

    const int mat = blockIdx.y;
    const float* W = (mat == 0) ? Wq : (mat == 1) ? Wk : Wv;
    uint32_t* out  = (mat == 0) ? g_q : (mat == 1) ? g_k : g_v;

    const int row0 = blockIdx.x * 128;
    const int tid  = threadIdx.x;
    const int wid  = tid >> 5, lane = tid & 31;
    const int g = lane >> 2, q = lane & 3;
    const int m0 = (wid & 3) * 32;    // warp rows
    const int n0 = (wid >> 2) * 64;   // warp cols

    float acc[2][8][4];
#pragma unroll
    for (int mt = 0; mt < 2; mt++)
#pragma unroll
        for (int nt = 0; nt < 8; nt++)
#pragma unroll
            for (int i = 0; i < 4; i++) acc[mt][nt][i] = 0.f;

    for (int k0 = 0; k0 < CC; k0 += 32) {
        // x tile 128x32 -> tf32 smem
#pragma unroll
        for (int t = 0; t < 4; t++) {
            int idx = tid + t * 256;          // 0..1023 float4s
            int r = idx >> 3, c4 = (idx & 7) * 4;
            float4 xv = *(const float4*)(x + (size_t)(row0 + r) * CC + k0 + c4);
            uint4 u = make_uint4(f2tf(xv.x), f2tf(xv.y), f2tf(xv.z), f2tf(xv.w));
            *(uint4*)&sX[r * PX_LD + c4] = u;
        }
        // W tile 32x128 -> tf32 smem
#pragma unroll
        for (int t = 0; t < 4; t++) {
            int idx = tid + t * 256;
            int r = idx >> 5, c4 = (idx & 31) * 4;
            float4 wv = *(const float4*)(W + (size_t)(k0 + r) * HH + c4);
            uint4 u = make_uint4(f2tf(wv.x), f2tf(wv.y), f2tf(wv.z), f2tf(wv.w));
            *(uint4*)&sW[r * PW_LD + c4] = u;
        }
        __syncthreads();

#pragma unroll
        for (int ks = 0; ks < 4; ks++) {
            int kk = ks * 8;
            uint32_t a[2][4];
#pragma unroll
            for (int mt = 0; mt < 2; mt++) {
                int mr = m0 + mt * 16;
                a[mt][0] = sX[(mr + g)     * PX_LD + kk + q];
                a[mt][1] = sX[(mr + g + 8) * PX_LD + kk + q];
                a[mt][2] = sX[(mr + g)     * PX_LD + kk + q + 4];
                a[mt][3] = sX[(mr + g + 8) * PX_LD + kk + q + 4];
            }
#pragma unroll
            for (int nt = 0; nt < 8; nt++) {
                uint32_t b0 = sW[(kk + q)     * PW_LD + n0 + nt * 8 + g];
                uint32_t b1 = sW[(kk + q + 4) * PW_LD + n0 + nt * 8 + g];
                mma8(acc[0][nt], a[0][0], a[0][1], a[0][2], a[0][3], b0, b1);
                mma8(acc[1][nt], a[1][0], a[1][1], a[1][2], a[1][3], b0, b1);
            }
        }
        __syncthreads();
    }

#pragma unroll
    for (int mt = 0; mt < 2; mt++)
#pragma unroll
        for (int nt = 0; nt < 8; nt++) {
            int r0 = row0 + m0 + mt * 16 + g;
            int c  = n0 + nt * 8 + 2 * q;
            uint2 lo = make_uint2(f2tf(acc[mt][nt][0]), f2tf(acc[mt][nt][1]));
            *(uint2*)&out[(size_t)r0 * HH + c] = lo;
            uint2 hi = make_uint2(f2tf(acc[mt][nt][2]), f2tf(acc[mt][nt][3]));
            *(uint2*)&out[(size_t)(r0 + 8) * HH + c] = hi;
        }
}

// ---------------------------------------------------------------------------
// Flash attention (causal), tf32 tensor cores, fp32 softmax.
// Block = (b, 64 q-rows), 256 thr (8 warps).
// S phase: warp tile 16x32 of 64x64. PV phase: warp tile 16x64 of 64x128.
// ---------------------------------------------------------------------------
__global__ __launch_bounds__(256) void flash_kernel(float* __restrict__ out)
{
    extern __shared__ uint32_t sm[];
    uint32_t* sQ = sm;                    // 64*LDT
    uint32_t* sK = sQ + 64 * LDT;         // 64*LDT
    uint32_t* sV = sK + 64 * LDT;         // 64*LDT
    float* sS   = (float*)(sV + 64 * LDT);   // 64*LDSS fp32
    float* mrow = sS + 64 * LDSS;
    float* lrow = mrow + 64;
    float* frow = lrow + 64;

    const int iq = gridDim.x - 1 - blockIdx.x;   // heavy tiles first
    const int b  = blockIdx.y;
    const int tid = threadIdx.x, wid = tid >> 5, lane = tid & 31;
    const int g = lane >> 2, q = lane & 3;
    const int m0 = (wid & 3) * 16;       // warp row base (both phases)
    const int wn = wid >> 2;             // warp col half

    const uint32_t* Qg = g_q + ((size_t)b * TT + iq * 64) * HH;
#pragma unroll
    for (int t = 0; t < 8; t++) {
        int idx = tid + t * 256;
        int r = idx >> 5, c4 = (idx & 31) * 4;
        *(uint4*)&sQ[r * LDT + c4] = *(const uint4*)(Qg + (size_t)r * HH + c4);
    }
    if (tid < 64) { mrow[tid] = -1e30f; lrow[tid] = 0.f; }

    float o[8][4];
#pragma unroll
    for (int nt = 0; nt < 8; nt++)
#pragma unroll
        for (int i = 0; i < 4; i++) o[nt][i] = 0.f;

    for (int jt = 0; jt <= iq; jt++) {
        __syncthreads();   // prev iter done with sK/sV/sS
        const uint32_t* Kg = g_k + ((size_t)b * TT + jt * 64) * HH;
        const uint32_t* Vg = g_v + ((size_t)b * TT + jt * 64) * HH;
#pragma unroll
        for (int t = 0; t < 8; t++) {
            int idx = tid + t * 256;
            int r = idx >> 5, c4 = (idx & 31) * 4;
            *(uint4*)&sK[r * LDT + c4] = *(const uint4*)(Kg + (size_t)r * HH + c4);
            *(uint4*)&sV[r * LDT + c4] = *(const uint4*)(Vg + (size_t)r * HH + c4);
        }
        __syncthreads();

        // ---- S = Q K^T (64x64, k=128) ----
        float sc[4][4];
#pragma unroll
        for (int nt = 0; nt < 4; nt++)
#pragma unroll
            for (int i = 0; i < 4; i++) sc[nt][i] = 0.f;

#pragma unroll
        for (int ks = 0; ks < 16; ks++) {
            int kk = ks * 8;
            uint32_t a0 = sQ[(m0 + g)     * LDT + kk + q];
            uint32_t a1 = sQ[(m0 + g + 8) * LDT + kk + q];
            uint32_t a2 = sQ[(m0 + g)     * LDT + kk + q + 4];
            uint32_t a3 = sQ[(m0 + g + 8) * LDT + kk + q + 4];
#pragma unroll
            for (int nt = 0; nt < 4; nt++) {
                int nc = wn * 32 + nt * 8;
                uint32_t b0 = sK[(nc + g) * LDT + kk + q];      // B[k][n]=K[n][k]
                uint32_t b1 = sK[(nc + g) * LDT + kk + q + 4];
                mma8(sc[nt], a0, a1, a2, a3, b0, b1);
            }
        }

        // mask + scale, spill to sS (fp32)
        {
            int grow0 = iq * 64 + m0 + g;
            int grow1 = grow0 + 8;
#pragma unroll
            for (int nt = 0; nt < 4; nt++) {
                int nc = wn * 32 + nt * 8;
                int gc = jt * 64 + nc + 2 * q;
                float2 v0;
                v0.x = (gc     <= grow0) ? sc[nt][0] * SCALE : -1e30f;
                v0.y = (gc + 1 <= grow0) ? sc[nt][1] * SCALE : -1e30f;
                *(float2*)&sS[(m0 + g) * LDSS + nc + 2 * q] = v0;
                float2 v1;
                v1.x = (gc     <= grow1) ? sc[nt][2] * SCALE : -1e30f;
                v1.y = (gc + 1 <= grow1) ? sc[nt][3] * SCALE : -1e30f;
                *(float2*)&sS[(m0 + g + 8) * LDSS + nc + 2 * q] = v1;
            }
        }
        __syncthreads();

        // ---- online softmax: 4 lanes/row, all 256 threads ----
        {
            int r = tid >> 2;
            int sub = tid & 3;
            float mold = mrow[r];
            float mt = mold;
#pragma unroll
            for (int j = 0; j < 16; j++)
                mt = fmaxf(mt, sS[r * LDSS + sub + 4 * j]);
            mt = fmaxf(mt, __shfl_xor_sync(0xFFFFFFFFu, mt, 1));
            mt = fmaxf(mt, __shfl_xor_sync(0xFFFFFFFFu, mt, 2));
            float ssum = 0.f;
#pragma unroll
            for (int j = 0; j < 16; j++) {
                float p = __expf(sS[r * LDSS + sub + 4 * j] - mt);
                sS[r * LDSS + sub + 4 * j] = p;
                ssum += p;
            }
            ssum += __shfl_xor_sync(0xFFFFFFFFu, ssum, 1);
            ssum += __shfl_xor_sync(0xFFFFFFFFu, ssum, 2);
            if (sub == 0) {
                float f = __expf(mold - mt);
                mrow[r] = mt;
                lrow[r] = lrow[r] * f + ssum;
                frow[r] = f;
            }
        }
        __syncthreads();

        // ---- rescale O, then O += P V (64x128, k=64) ----
        {
            float f0 = frow[m0 + g];
            float f1 = frow[m0 + g + 8];
#pragma unroll
            for (int nt = 0; nt < 8; nt++) {
                o[nt][0] *= f0; o[nt][1] *= f0;
                o[nt][2] *= f1; o[nt][3] *= f1;
            }
        }
#pragma unroll
        for (int ks = 0; ks < 8; ks++) {
            int kk = ks * 8;
            uint32_t a0 = f2tf(sS[(m0 + g)     * LDSS + kk + q]);
            uint32_t a1 = f2tf(sS[(m0 + g + 8) * LDSS + kk + q]);
            uint32_t a2 = f2tf(sS[(m0 + g)     * LDSS + kk + q + 4]);
            uint32_t a3 = f2tf(sS[(m0 + g + 8) * LDSS + kk + q + 4]);
#pragma unroll
            for (int nt = 0; nt < 8; nt++) {
                int nc = wn * 64 + nt * 8;
                uint32_t b0 = sV[(kk + q)     * LDT + nc + g];
                uint32_t b1 = sV[(kk + q + 4) * LDT + nc + g];
                mma8(o[nt], a0, a1, a2, a3, b0, b1);
            }
        }
    }

    __syncthreads();
    float il0 = 1.f / lrow[m0 + g];
    float il1 = 1.f / lrow[m0 + g + 8];
    float* Og = out + ((size_t)b * TT + iq * 64) * HH;
#pragma unroll
    for (int nt = 0; nt < 8; nt++) {
        int nc = wn * 64 + nt * 8 + 2 * q;
        float2 lo = make_float2(o[nt][0] * il0, o[nt][1] * il0);
        *(float2*)&Og[(size_t)(m0 + g) * HH + nc] = lo;
        float2 hi = make_float2(o[nt][2] * il1, o[nt][3] * il1);
        *(float2*)&Og[(size_t)(m0 + g + 8) * HH + nc] = hi;
    }
}

// ---------------------------------------------------------------------------
extern "C" void kernel_launch(void* const* d_in, const int* in_sizes, int n_in,
                              void* d_out, int out_size)
{
    const float* x  = (const float*)d_in[0];
    const float* Wk = (const float*)d_in[1];
    const float* Wq = (const float*)d_in[2];
    const float* Wv = (const float*)d_in[3];
    float* out = (float*)d_out;

    const int smem_bytes = (3 * 64 * LDT + 64 * LDSS + 3 * 64) * 4; // 119552
    (void)cudaFuncSetAttribute(flash_kernel,
                               cudaFuncAttributeMaxDynamicSharedMemorySize,
                               smem_bytes);

    dim3 g1(BT / 128, 3);
    proj_kernel<<<g1, 256>>>(x, Wk, Wq, Wv);

    dim3 g2(TT / 64, BB);
    flash_kernel<<<g2, 256, smem_bytes>>>(out);
}

// round 5
// speedup vs baseline: 2.6688x; 1.0915x over previous
#include <cuda_runtime.h>
#include <cstdint>

#define BB 8
#define TT 2048
#define CC 1024
#define HH 128
#define BT (BB*TT)
#define SCALE 0.08838834764831845f

#define PX_LD 36     // proj sX row stride (32 k + 4 pad)
#define PW_LD 136    // proj sW row stride (128 n + 8 pad)
#define LDT 132      // flash K/V row stride (128 + 4): bank = 4r+c, conflict-free
#define LDSS 68      // score tile row stride (64 + 4)

// q/k/v scratch stored as tf32 bit patterns (static device mem: allowed)
__device__ uint32_t g_q[BT * HH];
__device__ uint32_t g_k[BT * HH];
__device__ uint32_t g_v[BT * HH];

__device__ __forceinline__ uint32_t f2tf(float x) {
    uint32_t r;
    asm("cvt.rna.tf32.f32 %0, %1;" : "=r"(r) : "f"(x));
    return r;
}

// D += A*B, m16n8k8, A row-major 16x8 tf32, B col-major 8x8 tf32, fp32 accum
__device__ __forceinline__ void mma8(float* c, uint32_t a0, uint32_t a1,
                                     uint32_t a2, uint32_t a3,
                                     uint32_t b0, uint32_t b1) {
    asm volatile(
        "mma.sync.aligned.m16n8k8.row.col.f32.tf32.tf32.f32 "
        "{%0,%1,%2,%3},{%4,%5,%6,%7},{%8,%9},{%0,%1,%2,%3};"
        : "+f"(c[0]), "+f"(c[1]), "+f"(c[2]), "+f"(c[3])
        : "r"(a0), "r"(a1), "r"(a2), "r"(a3), "r"(b0), "r"(b1));
}

// ---------------------------------------------------------------------------
// Projection: out[mat] = tf32(x @ W[mat]).  M=16384, K=1024, N=128.
// (unchanged from R4 — isolate the flash change)
// ---------------------------------------------------------------------------
__global__ __launch_bounds__(256) void proj_kernel(
    const float* __restrict__ x,
    const float* __restrict__ Wk,
    const float* __restrict__ Wq,
    const float* __restrict__ Wv)
{
    __shared__ uint32_t sX[128 * PX_LD];
    __shared__ uint32_t sW[32 * PW_LD];

    const int mat = blockIdx.y;
    const float* W = (mat == 0) ? Wq : (mat == 1) ? Wk : Wv;
    uint32_t* out  = (mat == 0) ? g_q : (mat == 1) ? g_k : g_v;

    const int row0 = blockIdx.x * 128;
    const int tid  = threadIdx.x;
    const int wid  = tid >> 5, lane = tid & 31;
    const int g = lane >> 2, q = lane & 3;
    const int m0 = (wid & 3) * 32;
    const int n0 = (wid >> 2) * 64;

    float acc[2][8][4];
#pragma unroll
    for (int mt = 0; mt < 2; mt++)
#pragma unroll
        for (int nt = 0; nt < 8; nt++)
#pragma unroll
            for (int i = 0; i < 4; i++) acc[mt][nt][i] = 0.f;

    for (int k0 = 0; k0 < CC; k0 += 32) {
#pragma unroll
        for (int t = 0; t < 4; t++) {
            int idx = tid + t * 256;
            int r = idx >> 3, c4 = (idx & 7) * 4;
            float4 xv = *(const float4*)(x + (size_t)(row0 + r) * CC + k0 + c4);
            uint4 u = make_uint4(f2tf(xv.x), f2tf(xv.y), f2tf(xv.z), f2tf(xv.w));
            *(uint4*)&sX[r * PX_LD + c4] = u;
        }
#pragma unroll
        for (int t = 0; t < 4; t++) {
            int idx = tid + t * 256;
            int r = idx >> 5, c4 = (idx & 31) * 4;
            float4 wv = *(const float4*)(W + (size_t)(k0 + r) * HH + c4);
            uint4 u = make_uint4(f2tf(wv.x), f2tf(wv.y), f2tf(wv.z), f2tf(wv.w));
            *(uint4*)&sW[r * PW_LD + c4] = u;
        }
        __syncthreads();

#pragma unroll
        for (int ks = 0; ks < 4; ks++) {
            int kk = ks * 8;
            uint32_t a[2][4];
#pragma unroll
            for (int mt = 0; mt < 2; mt++) {
                int mr = m0 + mt * 16;
                a[mt][0] = sX[(mr + g)     * PX_LD + kk + q];
                a[mt][1] = sX[(mr + g + 8) * PX_LD + kk + q];
                a[mt][2] = sX[(mr + g)     * PX_LD + kk + q + 4];
                a[mt][3] = sX[(mr + g + 8) * PX_LD + kk + q + 4];
            }
#pragma unroll
            for (int nt = 0; nt < 8; nt++) {
                uint32_t b0 = sW[(kk + q)     * PW_LD + n0 + nt * 8 + g];
                uint32_t b1 = sW[(kk + q + 4) * PW_LD + n0 + nt * 8 + g];
                mma8(acc[0][nt], a[0][0], a[0][1], a[0][2], a[0][3], b0, b1);
                mma8(acc[1][nt], a[1][0], a[1][1], a[1][2], a[1][3], b0, b1);
            }
        }
        __syncthreads();
    }

#pragma unroll
    for (int mt = 0; mt < 2; mt++)
#pragma unroll
        for (int nt = 0; nt < 8; nt++) {
            int r0 = row0 + m0 + mt * 16 + g;
            int c  = n0 + nt * 8 + 2 * q;
            uint2 lo = make_uint2(f2tf(acc[mt][nt][0]), f2tf(acc[mt][nt][1]));
            *(uint2*)&out[(size_t)r0 * HH + c] = lo;
            uint2 hi = make_uint2(f2tf(acc[mt][nt][2]), f2tf(acc[mt][nt][3]));
            *(uint2*)&out[(size_t)(r0 + 8) * HH + c] = hi;
        }
}

// ---------------------------------------------------------------------------
// Flash attention (causal), tf32 mma, fp32 softmax.
// Q held in registers as prebuilt A-fragments (staged once through sK).
// smem = 85.8 KB -> 2 CTAs/SM for cross-CTA latency hiding.
// ---------------------------------------------------------------------------
__global__ __launch_bounds__(256) void flash_kernel(float* __restrict__ out)
{
    extern __shared__ uint32_t sm[];
    uint32_t* sK = sm;                    // 64*LDT
    uint32_t* sV = sK + 64 * LDT;         // 64*LDT
    float* sS   = (float*)(sV + 64 * LDT);   // 64*LDSS fp32
    float* mrow = sS + 64 * LDSS;
    float* lrow = mrow + 64;
    float* frow = lrow + 64;

    const int iq = gridDim.x - 1 - blockIdx.x;   // heavy tiles first
    const int b  = blockIdx.y;
    const int tid = threadIdx.x, wid = tid >> 5, lane = tid & 31;
    const int g = lane >> 2, q = lane & 3;
    const int m0 = (wid & 3) * 16;       // warp row base (both phases)
    const int wn = wid >> 2;             // warp col half

    // ---- stage Q through sK, build A-fragments in registers ----
    const uint32_t* Qg = g_q + ((size_t)b * TT + iq * 64) * HH;
#pragma unroll
    for (int t = 0; t < 8; t++) {
        int idx = tid + t * 256;
        int r = idx >> 5, c4 = (idx & 31) * 4;
        *(uint4*)&sK[r * LDT + c4] = *(const uint4*)(Qg + (size_t)r * HH + c4);
    }
    if (tid < 64) { mrow[tid] = -1e30f; lrow[tid] = 0.f; }
    __syncthreads();

    uint32_t aQ[16][4];
#pragma unroll
    for (int ks = 0; ks < 16; ks++) {
        int kk = ks * 8;
        aQ[ks][0] = sK[(m0 + g)     * LDT + kk + q];
        aQ[ks][1] = sK[(m0 + g + 8) * LDT + kk + q];
        aQ[ks][2] = sK[(m0 + g)     * LDT + kk + q + 4];
        aQ[ks][3] = sK[(m0 + g + 8) * LDT + kk + q + 4];
    }

    float o[8][4];
#pragma unroll
    for (int nt = 0; nt < 8; nt++)
#pragma unroll
        for (int i = 0; i < 4; i++) o[nt][i] = 0.f;

    for (int jt = 0; jt <= iq; jt++) {
        __syncthreads();   // frag-read / prev-iter sV reads done before overwrite
        const uint32_t* Kg = g_k + ((size_t)b * TT + jt * 64) * HH;
        const uint32_t* Vg = g_v + ((size_t)b * TT + jt * 64) * HH;
#pragma unroll
        for (int t = 0; t < 8; t++) {
            int idx = tid + t * 256;
            int r = idx >> 5, c4 = (idx & 31) * 4;
            *(uint4*)&sK[r * LDT + c4] = *(const uint4*)(Kg + (size_t)r * HH + c4);
            *(uint4*)&sV[r * LDT + c4] = *(const uint4*)(Vg + (size_t)r * HH + c4);
        }
        __syncthreads();

        // ---- S = Q K^T (64x64, k=128), A from registers ----
        float sc[4][4];
#pragma unroll
        for (int nt = 0; nt < 4; nt++)
#pragma unroll
            for (int i = 0; i < 4; i++) sc[nt][i] = 0.f;

#pragma unroll
        for (int ks = 0; ks < 16; ks++) {
            int kk = ks * 8;
#pragma unroll
            for (int nt = 0; nt < 4; nt++) {
                int nc = wn * 32 + nt * 8;
                uint32_t b0 = sK[(nc + g) * LDT + kk + q];      // B[k][n]=K[n][k]
                uint32_t b1 = sK[(nc + g) * LDT + kk + q + 4];
                mma8(sc[nt], aQ[ks][0], aQ[ks][1], aQ[ks][2], aQ[ks][3], b0, b1);
            }
        }

        // mask + scale, spill to sS (fp32)
        {
            int grow0 = iq * 64 + m0 + g;
            int grow1 = grow0 + 8;
#pragma unroll
            for (int nt = 0; nt < 4; nt++) {
                int nc = wn * 32 + nt * 8;
                int gc = jt * 64 + nc + 2 * q;
                float2 v0;
                v0.x = (gc     <= grow0) ? sc[nt][0] * SCALE : -1e30f;
                v0.y = (gc + 1 <= grow0) ? sc[nt][1] * SCALE : -1e30f;
                *(float2*)&sS[(m0 + g) * LDSS + nc + 2 * q] = v0;
                float2 v1;
                v1.x = (gc     <= grow1) ? sc[nt][2] * SCALE : -1e30f;
                v1.y = (gc + 1 <= grow1) ? sc[nt][3] * SCALE : -1e30f;
                *(float2*)&sS[(m0 + g + 8) * LDSS + nc + 2 * q] = v1;
            }
        }
        __syncthreads();

        // ---- online softmax: 4 lanes/row, all 256 threads ----
        {
            int r = tid >> 2;
            int sub = tid & 3;
            float mold = mrow[r];
            float mt = mold;
#pragma unroll
            for (int j = 0; j < 16; j++)
                mt = fmaxf(mt, sS[r * LDSS + sub + 4 * j]);
            mt = fmaxf(mt, __shfl_xor_sync(0xFFFFFFFFu, mt, 1));
            mt = fmaxf(mt, __shfl_xor_sync(0xFFFFFFFFu, mt, 2));
            float ssum = 0.f;
#pragma unroll
            for (int j = 0; j < 16; j++) {
                float p = __expf(sS[r * LDSS + sub + 4 * j] - mt);
                sS[r * LDSS + sub + 4 * j] = p;
                ssum += p;
            }
            ssum += __shfl_xor_sync(0xFFFFFFFFu, ssum, 1);
            ssum += __shfl_xor_sync(0xFFFFFFFFu, ssum, 2);
            if (sub == 0) {
                float f = __expf(mold - mt);
                mrow[r] = mt;
                lrow[r] = lrow[r] * f + ssum;
                frow[r] = f;
            }
        }
        __syncthreads();

        // ---- rescale O, then O += P V (64x128, k=64) ----
        {
            float f0 = frow[m0 + g];
            float f1 = frow[m0 + g + 8];
#pragma unroll
            for (int nt = 0; nt < 8; nt++) {
                o[nt][0] *= f0; o[nt][1] *= f0;
                o[nt][2] *= f1; o[nt][3] *= f1;
            }
        }
#pragma unroll
        for (int ks = 0; ks < 8; ks++) {
            int kk = ks * 8;
            uint32_t a0 = f2tf(sS[(m0 + g)     * LDSS + kk + q]);
            uint32_t a1 = f2tf(sS[(m0 + g + 8) * LDSS + kk + q]);
            uint32_t a2 = f2tf(sS[(m0 + g)     * LDSS + kk + q + 4]);
            uint32_t a3 = f2tf(sS[(m0 + g + 8) * LDSS + kk + q + 4]);
#pragma unroll
            for (int nt = 0; nt < 8; nt++) {
                int nc = wn * 64 + nt * 8;
                uint32_t b0 = sV[(kk + q)     * LDT + nc + g];
                uint32_t b1 = sV[(kk + q + 4) * LDT + nc + g];
                mma8(o[nt], a0, a1, a2, a3, b0, b1);
            }
        }
    }

    __syncthreads();
    float il0 = 1.f / lrow[m0 + g];
    float il1 = 1.f / lrow[m0 + g + 8];
    float* Og = out + ((size_t)b * TT + iq * 64) * HH;
#pragma unroll
    for (int nt = 0; nt < 8; nt++) {
        int nc = wn * 64 + nt * 8 + 2 * q;
        float2 lo = make_float2(o[nt][0] * il0, o[nt][1] * il0);
        *(float2*)&Og[(size_t)(m0 + g) * HH + nc] = lo;
        float2 hi = make_float2(o[nt][2] * il1, o[nt][3] * il1);
        *(float2*)&Og[(size_t)(m0 + g + 8) * HH + nc] = hi;
    }
}

// ---------------------------------------------------------------------------
extern "C" void kernel_launch(void* const* d_in, const int* in_sizes, int n_in,
                              void* d_out, int out_size)
{
    const float* x  = (const float*)d_in[0];
    const float* Wk = (const float*)d_in[1];
    const float* Wq = (const float*)d_in[2];
    const float* Wv = (const float*)d_in[3];
    float* out = (float*)d_out;

    const int smem_bytes = (2 * 64 * LDT + 64 * LDSS + 3 * 64) * 4; // 85760
    (void)cudaFuncSetAttribute(flash_kernel,
                               cudaFuncAttributeMaxDynamicSharedMemorySize,
                               smem_bytes);

    dim3 g1(BT / 128, 3);
    proj_kernel<<<g1, 256>>>(x, Wk, Wq, Wv);

    dim3 g2(TT / 64, BB);
    flash_kernel<<<g2, 256, smem_bytes>>>(out);
}

// round 6
// speedup vs baseline: 3.3099x; 1.2402x over previous
#include <cuda_runtime.h>
#include <cstdint>

#define BB 8
#define TT 2048
#define CC 1024
#define HH 128
#define BT (BB*TT)
#define SCALE 0.08838834764831845f

#define PX_LD 36     // proj sX row stride (32 k + 4 pad)
#define PW_LD 136    // proj sW row stride (128 n + 8 pad)
#define LDT 132      // flash K/V row stride (128 + 4)

// q/k/v scratch stored as tf32 bit patterns (static device mem: allowed)
__device__ uint32_t g_q[BT * HH];
__device__ uint32_t g_k[BT * HH];
__device__ uint32_t g_v[BT * HH];

__device__ __forceinline__ uint32_t f2tf(float x) {
    uint32_t r;
    asm("cvt.rna.tf32.f32 %0, %1;" : "=r"(r) : "f"(x));
    return r;
}

// D += A*B, m16n8k8, A row-major 16x8 tf32, B col-major 8x8 tf32, fp32 accum
__device__ __forceinline__ void mma8(float* c, uint32_t a0, uint32_t a1,
                                     uint32_t a2, uint32_t a3,
                                     uint32_t b0, uint32_t b1) {
    asm volatile(
        "mma.sync.aligned.m16n8k8.row.col.f32.tf32.tf32.f32 "
        "{%0,%1,%2,%3},{%4,%5,%6,%7},{%8,%9},{%0,%1,%2,%3};"
        : "+f"(c[0]), "+f"(c[1]), "+f"(c[2]), "+f"(c[3])
        : "r"(a0), "r"(a1), "r"(a2), "r"(a3), "r"(b0), "r"(b1));
}

// ---------------------------------------------------------------------------
// Projection: out[mat] = tf32(x @ W[mat]).  (unchanged from R5)
// ---------------------------------------------------------------------------
__global__ __launch_bounds__(256) void proj_kernel(
    const float* __restrict__ x,
    const float* __restrict__ Wk,
    const float* __restrict__ Wq,
    const float* __restrict__ Wv)
{
    __shared__ uint32_t sX[128 * PX_LD];
    __shared__ uint32_t sW[32 * PW_LD];

    const int mat = blockIdx.y;
    const float* W = (mat == 0) ? Wq : (mat == 1) ? Wk : Wv;
    uint32_t* out  = (mat == 0) ? g_q : (mat == 1) ? g_k : g_v;

    const int row0 = blockIdx.x * 128;
    const int tid  = threadIdx.x;
    const int wid  = tid >> 5, lane = tid & 31;
    const int g = lane >> 2, q = lane & 3;
    const int m0 = (wid & 3) * 32;
    const int n0 = (wid >> 2) * 64;

    float acc[2][8][4];
#pragma unroll
    for (int mt = 0; mt < 2; mt++)
#pragma unroll
        for (int nt = 0; nt < 8; nt++)
#pragma unroll
            for (int i = 0; i < 4; i++) acc[mt][nt][i] = 0.f;

    for (int k0 = 0; k0 < CC; k0 += 32) {
#pragma unroll
        for (int t = 0; t < 4; t++) {
            int idx = tid + t * 256;
            int r = idx >> 3, c4 = (idx & 7) * 4;
            float4 xv = *(const float4*)(x + (size_t)(row0 + r) * CC + k0 + c4);
            uint4 u = make_uint4(f2tf(xv.x), f2tf(xv.y), f2tf(xv.z), f2tf(xv.w));
            *(uint4*)&sX[r * PX_LD + c4] = u;
        }
#pragma unroll
        for (int t = 0; t < 4; t++) {
            int idx = tid + t * 256;
            int r = idx >> 5, c4 = (idx & 31) * 4;
            float4 wv = *(const float4*)(W + (size_t)(k0 + r) * HH + c4);
            uint4 u = make_uint4(f2tf(wv.x), f2tf(wv.y), f2tf(wv.z), f2tf(wv.w));
            *(uint4*)&sW[r * PW_LD + c4] = u;
        }
        __syncthreads();

#pragma unroll
        for (int ks = 0; ks < 4; ks++) {
            int kk = ks * 8;
            uint32_t a[2][4];
#pragma unroll
            for (int mt = 0; mt < 2; mt++) {
                int mr = m0 + mt * 16;
                a[mt][0] = sX[(mr + g)     * PX_LD + kk + q];
                a[mt][1] = sX[(mr + g + 8) * PX_LD + kk + q];
                a[mt][2] = sX[(mr + g)     * PX_LD + kk + q + 4];
                a[mt][3] = sX[(mr + g + 8) * PX_LD + kk + q + 4];
            }
#pragma unroll
            for (int nt = 0; nt < 8; nt++) {
                uint32_t b0 = sW[(kk + q)     * PW_LD + n0 + nt * 8 + g];
                uint32_t b1 = sW[(kk + q + 4) * PW_LD + n0 + nt * 8 + g];
                mma8(acc[0][nt], a[0][0], a[0][1], a[0][2], a[0][3], b0, b1);
                mma8(acc[1][nt], a[1][0], a[1][1], a[1][2], a[1][3], b0, b1);
            }
        }
        __syncthreads();
    }

#pragma unroll
    for (int mt = 0; mt < 2; mt++)
#pragma unroll
        for (int nt = 0; nt < 8; nt++) {
            int r0 = row0 + m0 + mt * 16 + g;
            int c  = n0 + nt * 8 + 2 * q;
            uint2 lo = make_uint2(f2tf(acc[mt][nt][0]), f2tf(acc[mt][nt][1]));
            *(uint2*)&out[(size_t)r0 * HH + c] = lo;
            uint2 hi = make_uint2(f2tf(acc[mt][nt][2]), f2tf(acc[mt][nt][3]));
            *(uint2*)&out[(size_t)(r0 + 8) * HH + c] = hi;
        }
}

// ---------------------------------------------------------------------------
// Flash attention (causal). Two independent 128-thread halves per block:
// half 0 -> q-tile p, half 1 -> q-tile 31-p (perfect 33-iter balance).
// Warp = full 16x64 S row-strip: register softmax, register P (shuffle
// C->A conversion), zero block-wide barriers; named barrier per half.
// ---------------------------------------------------------------------------
#define HALF_WORDS (2 * 64 * LDT)   // K + V tiles for one half

__global__ __launch_bounds__(256, 1) void flash_kernel(float* __restrict__ out)
{
    extern __shared__ uint32_t sm[];

    const int tid  = threadIdx.x;
    const int half = tid >> 7;            // 0 or 1
    const int tid_h = tid & 127;
    const int hw   = (tid >> 5) & 3;      // warp within half
    const int lane = tid & 31;
    const int g = lane >> 2, q = lane & 3;

    const int p  = blockIdx.x;            // 0..15
    const int b  = blockIdx.y;
    const int iq = half ? (31 - p) : p;    // q-tile (64 rows)

    uint32_t* sK = sm + half * HALF_WORDS;
    uint32_t* sV = sK + 64 * LDT;

    // ---- Q fragments straight from gmem (once) ----
    const uint32_t* Qg = g_q + ((size_t)b * TT + iq * 64 + hw * 16) * HH;
    uint32_t aQ[16][4];
#pragma unroll
    for (int ks = 0; ks < 16; ks++) {
        int kk = ks * 8;
        aQ[ks][0] = Qg[(size_t)(g)     * HH + kk + q];
        aQ[ks][1] = Qg[(size_t)(g + 8) * HH + kk + q];
        aQ[ks][2] = Qg[(size_t)(g)     * HH + kk + q + 4];
        aQ[ks][3] = Qg[(size_t)(g + 8) * HH + kk + q + 4];
    }

    float o[16][4];
#pragma unroll
    for (int nt = 0; nt < 16; nt++)
#pragma unroll
        for (int i = 0; i < 4; i++) o[nt][i] = 0.f;
    float m0 = -1e30f, m1 = -1e30f, l0 = 0.f, l1 = 0.f;

    const int lr0 = hw * 16 + g;       // local rows within the 64-row q-tile
    const int lr1 = lr0 + 8;

    for (int jt = 0; jt <= iq; jt++) {
        // prior iteration's reads of sK/sV are done
        asm volatile("bar.sync %0, %1;" :: "r"(half + 1), "r"(128) : "memory");

        const uint32_t* Kg = g_k + ((size_t)b * TT + jt * 64) * HH;
        const uint32_t* Vg = g_v + ((size_t)b * TT + jt * 64) * HH;
#pragma unroll
        for (int t = 0; t < 16; t++) {
            int idx = tid_h + t * 128;
            int r = idx >> 5, c4 = (idx & 31) * 4;
            *(uint4*)&sK[r * LDT + c4] = *(const uint4*)(Kg + (size_t)r * HH + c4);
            *(uint4*)&sV[r * LDT + c4] = *(const uint4*)(Vg + (size_t)r * HH + c4);
        }
        asm volatile("bar.sync %0, %1;" :: "r"(half + 1), "r"(128) : "memory");

        // ---- S = Q K^T : warp strip 16 x 64, k=128 ----
        float sc[8][4];
#pragma unroll
        for (int nt = 0; nt < 8; nt++)
#pragma unroll
            for (int i = 0; i < 4; i++) sc[nt][i] = 0.f;

#pragma unroll
        for (int ks = 0; ks < 16; ks++) {
            int kk = ks * 8;
#pragma unroll
            for (int nt = 0; nt < 8; nt++) {
                uint32_t b0 = sK[(nt * 8 + g) * LDT + kk + q];
                uint32_t b1 = sK[(nt * 8 + g) * LDT + kk + q + 4];
                mma8(sc[nt], aQ[ks][0], aQ[ks][1], aQ[ks][2], aQ[ks][3], b0, b1);
            }
        }

        // scale (+ causal mask only on the diagonal tile jt == iq)
#pragma unroll
        for (int nt = 0; nt < 8; nt++)
#pragma unroll
            for (int i = 0; i < 4; i++) sc[nt][i] *= SCALE;
        if (jt == iq) {
#pragma unroll
            for (int nt = 0; nt < 8; nt++) {
                int c = nt * 8 + 2 * q;
                if (c     > lr0) sc[nt][0] = -1e30f;
                if (c + 1 > lr0) sc[nt][1] = -1e30f;
                if (c     > lr1) sc[nt][2] = -1e30f;
                if (c + 1 > lr1) sc[nt][3] = -1e30f;
            }
        }

        // ---- warp-local online softmax (rows g and g+8) ----
        float mt0 = -1e30f, mt1 = -1e30f;
#pragma unroll
        for (int nt = 0; nt < 8; nt++) {
            mt0 = fmaxf(mt0, fmaxf(sc[nt][0], sc[nt][1]));
            mt1 = fmaxf(mt1, fmaxf(sc[nt][2], sc[nt][3]));
        }
        mt0 = fmaxf(mt0, __shfl_xor_sync(0xFFFFFFFFu, mt0, 1));
        mt0 = fmaxf(mt0, __shfl_xor_sync(0xFFFFFFFFu, mt0, 2));
        mt1 = fmaxf(mt1, __shfl_xor_sync(0xFFFFFFFFu, mt1, 1));
        mt1 = fmaxf(mt1, __shfl_xor_sync(0xFFFFFFFFu, mt1, 2));
        float mn0 = fmaxf(m0, mt0), mn1 = fmaxf(m1, mt1);
        float f0 = __expf(m0 - mn0), f1 = __expf(m1 - mn1);
        m0 = mn0; m1 = mn1;

        float s0 = 0.f, s1 = 0.f;
#pragma unroll
        for (int nt = 0; nt < 8; nt++) {
            sc[nt][0] = __expf(sc[nt][0] - mn0); s0 += sc[nt][0];
            sc[nt][1] = __expf(sc[nt][1] - mn0); s0 += sc[nt][1];
            sc[nt][2] = __expf(sc[nt][2] - mn1); s1 += sc[nt][2];
            sc[nt][3] = __expf(sc[nt][3] - mn1); s1 += sc[nt][3];
        }
        s0 += __shfl_xor_sync(0xFFFFFFFFu, s0, 1);
        s0 += __shfl_xor_sync(0xFFFFFFFFu, s0, 2);
        s1 += __shfl_xor_sync(0xFFFFFFFFu, s1, 1);
        s1 += __shfl_xor_sync(0xFFFFFFFFu, s1, 2);
        l0 = l0 * f0 + s0;
        l1 = l1 * f1 + s1;

#pragma unroll
        for (int nt = 0; nt < 16; nt++) {
            o[nt][0] *= f0; o[nt][1] *= f0;
            o[nt][2] *= f1; o[nt][3] *= f1;
        }

        // ---- O += P V : P from registers via shuffle C->A conversion ----
        const int src1 = (lane & ~3) | (q >> 1);
        const int src2 = src1 + 2;
        const bool odd = (q & 1);
#pragma unroll
        for (int ks = 0; ks < 8; ks++) {
            float t0 = __shfl_sync(0xFFFFFFFFu, sc[ks][0], src1);
            float t1 = __shfl_sync(0xFFFFFFFFu, sc[ks][1], src1);
            float t2 = __shfl_sync(0xFFFFFFFFu, sc[ks][2], src1);
            float t3 = __shfl_sync(0xFFFFFFFFu, sc[ks][3], src1);
            float u0 = __shfl_sync(0xFFFFFFFFu, sc[ks][0], src2);
            float u1 = __shfl_sync(0xFFFFFFFFu, sc[ks][1], src2);
            float u2 = __shfl_sync(0xFFFFFFFFu, sc[ks][2], src2);
            float u3 = __shfl_sync(0xFFFFFFFFu, sc[ks][3], src2);
            uint32_t a0 = f2tf(odd ? t1 : t0);
            uint32_t a1 = f2tf(odd ? t3 : t2);
            uint32_t a2 = f2tf(odd ? u1 : u0);
            uint32_t a3 = f2tf(odd ? u3 : u2);
            int kk = ks * 8;
#pragma unroll
            for (int nt = 0; nt < 16; nt++) {
                uint32_t b0 = sV[(kk + q)     * LDT + nt * 8 + g];
                uint32_t b1 = sV[(kk + q + 4) * LDT + nt * 8 + g];
                mma8(o[nt], a0, a1, a2, a3, b0, b1);
            }
        }
    }

    // ---- epilogue (warp-local) ----
    float il0 = 1.f / l0, il1 = 1.f / l1;
    float* Og = out + ((size_t)b * TT + iq * 64 + hw * 16) * HH;
#pragma unroll
    for (int nt = 0; nt < 16; nt++) {
        int c = nt * 8 + 2 * q;
        float2 lo = make_float2(o[nt][0] * il0, o[nt][1] * il0);
        *(float2*)&Og[(size_t)g * HH + c] = lo;
        float2 hi = make_float2(o[nt][2] * il1, o[nt][3] * il1);
        *(float2*)&Og[(size_t)(g + 8) * HH + c] = hi;
    }
}

// ---------------------------------------------------------------------------
extern "C" void kernel_launch(void* const* d_in, const int* in_sizes, int n_in,
                              void* d_out, int out_size)
{
    const float* x  = (const float*)d_in[0];
    const float* Wk = (const float*)d_in[1];
    const float* Wq = (const float*)d_in[2];
    const float* Wv = (const float*)d_in[3];
    float* out = (float*)d_out;

    const int smem_bytes = 2 * HALF_WORDS * 4;   // 135168
    (void)cudaFuncSetAttribute(flash_kernel,
                               cudaFuncAttributeMaxDynamicSharedMemorySize,
                               smem_bytes);

    dim3 g1(BT / 128, 3);
    proj_kernel<<<g1, 256>>>(x, Wk, Wq, Wv);

    dim3 g2(TT / 128, BB);   // 16 pairs x 8 batches = 128 blocks
    flash_kernel<<<g2, 256, smem_bytes>>>(out);
}